// round 1
// baseline (speedup 1.0000x reference)
#include <cuda_runtime.h>
#include <math_constants.h>

// Problem constants
#define NB      4
#define NDET    128
#define NT      2048
#define NPIX    65536            // 256*256
#define DC      4                // dets per chunk (SMEM = DC*NT*16B = 128KB)
#define NCHUNK  32               // NDET / DC
#define PT      32               // pixel tiles
#define PIX_PER_TILE 2048        // NPIX / PT
#define THREADS 512

// Scratch (no allocations allowed in kernel_launch)
__device__ float4 g_sino_t[NDET * NT];    // [d][k] -> (s_b0, s_b1, s_b2, s_b3)   4 MB
__device__ float4 g_part[NCHUNK * NPIX];  // [chunk][pixel] -> per-batch partials 32 MB

// ---------------------------------------------------------------------------
// Kernel 1: transpose sino (B,1,NDET,NT) -> [d][k] float4 over batches.
// Reads coalesced along k per batch; writes coalesced float4.
// ---------------------------------------------------------------------------
__global__ void sino_transpose_kernel(const float* __restrict__ sino) {
    int idx = blockIdx.x * blockDim.x + threadIdx.x;   // idx = d*NT + k
    if (idx >= NDET * NT) return;
    float4 v;
    v.x = sino[0 * NDET * NT + idx];
    v.y = sino[1 * NDET * NT + idx];
    v.z = sino[2 * NDET * NT + idx];
    v.w = sino[3 * NDET * NT + idx];
    g_sino_t[idx] = v;
}

// ---------------------------------------------------------------------------
// Kernel 2: main backprojection.
// grid = (PT pixel-tiles, NCHUNK det-chunks). Each block stages DC det rows
// (all batches, float4 per k) into SMEM (128 KB), then each thread handles
// 4 pixels: load 4 dets' lut as 2 adjacent float4 (one full 32B sector),
// gather 2 LDS.128 per det from SMEM, accumulate 4 batch sums, write one
// float4 partial. Deterministic (no atomics).
// ---------------------------------------------------------------------------
extern __shared__ float4 s_sino[];   // [DC][NT]

__global__ void __launch_bounds__(THREADS, 1)
bp_main_kernel(const float4* __restrict__ lut4) {
    const int tid = threadIdx.x;
    const int pt  = blockIdx.x;          // pixel tile
    const int c   = blockIdx.y;          // det chunk

    // Stage sino chunk: contiguous 128 KB copy, fully coalesced.
    const float4* __restrict__ src = g_sino_t + (size_t)c * (DC * NT);
    #pragma unroll 4
    for (int i = tid; i < DC * NT; i += THREADS) {
        s_sino[i] = src[i];
    }

    // Hann window weights for this chunk's 4 dets (norm applied at reduce).
    float apod[DC];
    #pragma unroll
    for (int j = 0; j < DC; j++) {
        int d = c * DC + j;
        apod[j] = 0.5f - 0.5f * cosf(6.2831853071795864769f * (float)d / 127.0f);
    }

    __syncthreads();

    #pragma unroll
    for (int pp = 0; pp < PIX_PER_TILE / THREADS; pp++) {
        const int p = pt * PIX_PER_TILE + pp * THREADS + tid;

        // lut layout: [pixel][det][2] floats -> 64 float4 per pixel.
        // This chunk's 4 dets = 2 adjacent float4 (32B, 32B-aligned).
        const size_t lbase = (size_t)p * 64 + (size_t)c * 2;
        float4 la = lut4[lbase];
        float4 lb = lut4[lbase + 1];

        float kf[DC] = {la.x, la.z, lb.x, lb.z};
        float al[DC] = {la.y, la.w, lb.y, lb.w};

        float4 acc = make_float4(0.f, 0.f, 0.f, 0.f);

        #pragma unroll
        for (int j = 0; j < DC; j++) {
            int k = (int)kf[j];
            // valid = (k >= 0) && (k < NT-1); unsigned compare handles negatives
            bool valid = ((unsigned)k < (unsigned)(NT - 1));
            int k0 = min(max(k, 0), NT - 2);

            float4 s0 = s_sino[j * NT + k0];
            float4 s1 = s_sino[j * NT + k0 + 1];

            float w  = valid ? apod[j] : 0.0f;
            float wa = w * al[j];
            float w0 = w - wa;

            acc.x = fmaf(w0, s0.x, fmaf(wa, s1.x, acc.x));
            acc.y = fmaf(w0, s0.y, fmaf(wa, s1.y, acc.y));
            acc.z = fmaf(w0, s0.z, fmaf(wa, s1.z, acc.z));
            acc.w = fmaf(w0, s0.w, fmaf(wa, s1.w, acc.w));
        }

        g_part[(size_t)c * NPIX + p] = acc;   // coalesced float4 store
    }
}

// ---------------------------------------------------------------------------
// Kernel 3: reduce partials over chunks, normalize, write output (B,1,NY,NX).
// ---------------------------------------------------------------------------
__global__ void bp_reduce_kernel(float* __restrict__ out) {
    int p = blockIdx.x * blockDim.x + threadIdx.x;
    if (p >= NPIX) return;
    float4 acc = make_float4(0.f, 0.f, 0.f, 0.f);
    #pragma unroll
    for (int c = 0; c < NCHUNK; c++) {
        float4 v = g_part[(size_t)c * NPIX + p];
        acc.x += v.x; acc.y += v.y; acc.z += v.z; acc.w += v.w;
    }
    // norm = sum_d apod[d] = 64 - 0.5*sum(cos) = 63.5 exactly (geometric sum = 1)
    const float inv_norm = 1.0f / 63.5f;
    out[0 * NPIX + p] = acc.x * inv_norm;
    out[1 * NPIX + p] = acc.y * inv_norm;
    out[2 * NPIX + p] = acc.z * inv_norm;
    out[3 * NPIX + p] = acc.w * inv_norm;
}

// ---------------------------------------------------------------------------
extern "C" void kernel_launch(void* const* d_in, const int* in_sizes, int n_in,
                              void* d_out, int out_size) {
    const float*  sino = (const float*)d_in[0];
    const float4* lut4 = (const float4*)d_in[1];
    float*        out  = (float*)d_out;

    // 128 KB dynamic SMEM for the main kernel (idempotent, capture-safe)
    cudaFuncSetAttribute(bp_main_kernel,
                         cudaFuncAttributeMaxDynamicSharedMemorySize,
                         DC * NT * (int)sizeof(float4));

    sino_transpose_kernel<<<(NDET * NT + 255) / 256, 256>>>(sino);

    dim3 grid(PT, NCHUNK);
    bp_main_kernel<<<grid, THREADS, DC * NT * sizeof(float4)>>>(lut4);

    bp_reduce_kernel<<<(NPIX + 255) / 256, 256>>>(out);
}